// round 7
// baseline (speedup 1.0000x reference)
#include <cuda_runtime.h>
#include <cuda_bf16.h>
#include <cstdint>
#include <math.h>

// ---------------------------------------------------------------------------
// Problem constants
// ---------------------------------------------------------------------------
#define NHALF 8192
#define NROWS 16384
#define DDIM 256
#define TILE 128
#define NT (NROWS / TILE)          // 128 j-tiles
#define INV_TAU_LOG2E 2.8853900817779268f   // (1/tau) * log2(e), tau = 0.5
#define E2 7.38905609893065f                // exp(2.0) = refl diagonal
#define LN2F 0.6931471805599453f

#define TILE_BYTES (TILE * DDIM * 2)        // 65536 bytes (128 rows x 256 bf16)

// Scratch (static device arrays; no allocations allowed)
__device__ __align__(256) __nv_bfloat16 g_X[NROWS * DDIM];   // 8 MB normalized bf16
__device__ float g_rowsum[NROWS];
__device__ float g_posdot[NHALF];

// ---------------------------------------------------------------------------
// PTX helpers (plain sm_103-legal ISA only: ldmatrix / mma.sync / cp.async)
// ---------------------------------------------------------------------------
__device__ __forceinline__ float ex2_approx(float x) {
    float r;
    asm("ex2.approx.ftz.f32 %0, %1;" : "=f"(r) : "f"(x));
    return r;
}

__device__ __forceinline__ float lg2_approx(float x) {
    float r;
    asm("lg2.approx.ftz.f32 %0, %1;" : "=f"(r) : "f"(x));
    return r;
}

__device__ __forceinline__ uint32_t smem_u32(const void* p) {
    uint32_t a;
    asm("{ .reg .u64 t; cvta.to.shared.u64 t, %1; cvt.u32.u64 %0, t; }" : "=r"(a) : "l"(p));
    return a;
}

#define CP_COMMIT() asm volatile("cp.async.commit_group;" ::: "memory")
#define CP_WAIT1()  asm volatile("cp.async.wait_group 1;" ::: "memory")
#define CP_WAIT0()  asm volatile("cp.async.wait_group 0;" ::: "memory")

// Blocked-atom SW128 address for element (row, colb16) inside a 128x256 bf16 tile.
// Atom = 8 rows x 64 bf16 (1024B); atom grid 16 (rows) x 4 (cols), col stride 16 atoms.
__device__ __forceinline__ uint32_t tile_addr(uint32_t base, int row, int colb16) {
    uint32_t byte = (uint32_t)(((row >> 3) + (colb16 >> 6) * 16) * 1024 +
                               (row & 7) * 128 + (colb16 & 63) * 2);
    byte ^= (byte >> 3) & 0x70;            // SW128 swizzle
    return base + byte;
}

// Async-copy one 128x256 bf16 tile (global, row-major) into blocked-atom SW128 SMEM.
// 4096 16B chunks, 256 threads -> 16 chunks each, coalesced 16B cp.async.
__device__ __forceinline__ void cp_tile_async(uint32_t dst_base, const char* __restrict__ src,
                                              int tid) {
#pragma unroll
    for (int k = 0; k < 16; ++k) {
        int idx = tid + k * 256;               // row*32 + q
        int row = idx >> 5;
        int q = idx & 31;                      // 16B chunk within 512B logical row
        uint32_t byte = (uint32_t)(((row >> 3) + (q >> 3) * 16) * 1024 +
                                   (row & 7) * 128 + (q & 7) * 16);
        byte ^= (byte >> 3) & 0x70;
        asm volatile("cp.async.cg.shared.global [%0], [%1], 16;"
                     :: "r"(dst_base + byte), "l"(src + (size_t)idx * 16) : "memory");
    }
}

__device__ __forceinline__ void ldsm_x4(uint32_t addr, uint32_t& r0, uint32_t& r1,
                                        uint32_t& r2, uint32_t& r3) {
    asm volatile("ldmatrix.sync.aligned.m8n8.x4.shared.b16 {%0,%1,%2,%3}, [%4];"
                 : "=r"(r0), "=r"(r1), "=r"(r2), "=r"(r3) : "r"(addr));
}

__device__ __forceinline__ void mma16816(float& c0, float& c1, float& c2, float& c3,
                                         uint32_t a0, uint32_t a1, uint32_t a2, uint32_t a3,
                                         uint32_t b0, uint32_t b1) {
    asm volatile("mma.sync.aligned.m16n8k16.row.col.f32.bf16.bf16.f32 "
                 "{%0,%1,%2,%3}, {%4,%5,%6,%7}, {%8,%9}, {%0,%1,%2,%3};"
                 : "+f"(c0), "+f"(c1), "+f"(c2), "+f"(c3)
                 : "r"(a0), "r"(a1), "r"(a2), "r"(a3), "r"(b0), "r"(b1));
}

// ---------------------------------------------------------------------------
// SMEM layout for GEMM kernel
// ---------------------------------------------------------------------------
#define SM_A 0
#define SM_B0 65536
#define SM_B1 131072
#define SM_RED 196608
#define SM_TOTAL (SM_RED + 512)   // 197120 bytes -> 1 CTA/SM

// ---------------------------------------------------------------------------
// Kernel 1: normalize rows, write bf16 X = [an; bn], compute pos dot (fp32)
// ---------------------------------------------------------------------------
__global__ void __launch_bounds__(DDIM) normalize_kernel(const float* __restrict__ z1,
                                                          const float* __restrict__ z2) {
    const int i = blockIdx.x;
    const int t = threadIdx.x;
    const int w = t >> 5, l = t & 31;
    __shared__ float sha[8], shb[8], shd[8];
    __shared__ float s_ia, s_ib;

    float a = z1[(size_t)i * DDIM + t];
    float b = z2[(size_t)i * DDIM + t];
    float va = a * a, vb = b * b, vd = a * b;
#pragma unroll
    for (int o = 16; o; o >>= 1) {
        va += __shfl_xor_sync(0xffffffffu, va, o);
        vb += __shfl_xor_sync(0xffffffffu, vb, o);
        vd += __shfl_xor_sync(0xffffffffu, vd, o);
    }
    if (l == 0) { sha[w] = va; shb[w] = vb; shd[w] = vd; }
    __syncthreads();
    if (t == 0) {
        float sa = 0.f, sb = 0.f, sd = 0.f;
        for (int k = 0; k < 8; ++k) { sa += sha[k]; sb += shb[k]; sd += shd[k]; }
        float ia = rsqrtf(fmaxf(sa, 1e-24f));   // norms ~16 >> eps
        float ib = rsqrtf(fmaxf(sb, 1e-24f));
        s_ia = ia; s_ib = ib;
        g_posdot[i] = sd * ia * ib;             // an_i . bn_i in fp32
    }
    __syncthreads();
    g_X[(size_t)i * DDIM + t]           = __float2bfloat16(a * s_ia);
    g_X[(size_t)(NHALF + i) * DDIM + t] = __float2bfloat16(b * s_ib);
}

// ---------------------------------------------------------------------------
// Kernel 2: per-row sums of exp(X X^T / tau) via mma.sync (HMMA bf16).
// 128 CTAs x 256 threads. CTA = 128-row strip; loops 128 j-tiles of 128 cols.
// A strip resident in SMEM; B double-buffered via cp.async (1-tile lookahead).
// Warp grid 2(m) x 4(n); warp tile 64x32; m16n8k16 frags via ldmatrix.x4.
// ---------------------------------------------------------------------------
__global__ void __launch_bounds__(256, 1) gemm_rowsum_kernel() {
    extern __shared__ char smem[];
    const uint32_t sbase = smem_u32(smem);
    const int tid = threadIdx.x;
    const int wid = tid >> 5, lane = tid & 31;
    const int ib = blockIdx.x;

    const int wm = wid >> 2;          // 0..1: 64-row half of the strip
    const int wn = wid & 3;           // 0..3: 32-col quarter of the j-tile

    float* red = reinterpret_cast<float*>(smem + SM_RED);
    if (tid < TILE) red[tid] = 0.0f;

    const char* Xb = reinterpret_cast<const char*>(g_X);

    // Prime the pipeline: A strip (group0), B0 (group1), B1 (group2)
    cp_tile_async(sbase + SM_A, Xb + (size_t)ib * TILE_BYTES, tid);
    CP_COMMIT();
    cp_tile_async(sbase + SM_B0, Xb, tid);
    CP_COMMIT();
    cp_tile_async(sbase + SM_B1, Xb + TILE_BYTES, tid);
    CP_COMMIT();

    // ldmatrix per-thread address components
    const int a_row_in = lane & 15;           // + wm*64 + mf*16
    const int a_col_in = (lane >> 4) * 8;     // + ks*16
    const int b_row_in = (lane & 7) + ((lane >> 4) & 1) * 8;   // + wn*32 + p*16
    const int b_col_in = ((lane >> 3) & 1) * 8;                // + ks*16

    float rowacc[8];
#pragma unroll
    for (int i = 0; i < 8; ++i) rowacc[i] = 0.0f;

    for (int t = 0; t < NT; ++t) {
        CP_WAIT1();            // B(t) (and A) complete; only B(t+1) may pend
        __syncthreads();

        const uint32_t bbase = sbase + ((t & 1) ? SM_B1 : SM_B0);

        float c[4][4][4];
#pragma unroll
        for (int mf = 0; mf < 4; ++mf)
#pragma unroll
            for (int nf = 0; nf < 4; ++nf)
#pragma unroll
                for (int r = 0; r < 4; ++r) c[mf][nf][r] = 0.0f;

#pragma unroll
        for (int ks = 0; ks < 16; ++ks) {
            const int kcol = ks * 16;
            uint32_t a[4][4];
#pragma unroll
            for (int mf = 0; mf < 4; ++mf)
                ldsm_x4(tile_addr(sbase + SM_A, wm * 64 + mf * 16 + a_row_in,
                                  kcol + a_col_in),
                        a[mf][0], a[mf][1], a[mf][2], a[mf][3]);
            uint32_t b[4][2];
#pragma unroll
            for (int p = 0; p < 2; ++p) {
                uint32_t r0, r1, r2, r3;
                ldsm_x4(tile_addr(bbase, wn * 32 + p * 16 + b_row_in,
                                  kcol + b_col_in),
                        r0, r1, r2, r3);
                b[p * 2 + 0][0] = r0; b[p * 2 + 0][1] = r1;
                b[p * 2 + 1][0] = r2; b[p * 2 + 1][1] = r3;
            }
#pragma unroll
            for (int mf = 0; mf < 4; ++mf)
#pragma unroll
                for (int nf = 0; nf < 4; ++nf)
                    mma16816(c[mf][nf][0], c[mf][nf][1], c[mf][nf][2], c[mf][nf][3],
                             a[mf][0], a[mf][1], a[mf][2], a[mf][3],
                             b[nf][0], b[nf][1]);
        }

        // exp epilogue: c0,c1 -> row base; c2,c3 -> row base+8
#pragma unroll
        for (int mf = 0; mf < 4; ++mf) {
            float s0 = 0.f, s1 = 0.f;
#pragma unroll
            for (int nf = 0; nf < 4; ++nf) {
                s0 += ex2_approx(c[mf][nf][0] * INV_TAU_LOG2E)
                    + ex2_approx(c[mf][nf][1] * INV_TAU_LOG2E);
                s1 += ex2_approx(c[mf][nf][2] * INV_TAU_LOG2E)
                    + ex2_approx(c[mf][nf][3] * INV_TAU_LOG2E);
            }
            rowacc[mf * 2 + 0] += s0;
            rowacc[mf * 2 + 1] += s1;
        }

        __syncthreads();       // everyone done reading buf[t&1]
        if (t + 2 < NT) {
            cp_tile_async(bbase, Xb + (size_t)(t + 2) * TILE_BYTES, tid);
            CP_COMMIT();
        }
    }
    CP_WAIT0();

    // Reduce: 4 lanes (same lane>>2) share each row; then combine 4 n-warps.
#pragma unroll
    for (int i = 0; i < 8; ++i) {
        float v = rowacc[i];
        v += __shfl_xor_sync(0xffffffffu, v, 1);
        v += __shfl_xor_sync(0xffffffffu, v, 2);
        if ((lane & 3) == 0) {
            int row = wm * 64 + (i >> 1) * 16 + (lane >> 2) + (i & 1) * 8;
            atomicAdd(&red[row], v);
        }
    }
    __syncthreads();
    if (tid < TILE) g_rowsum[(size_t)ib * TILE + tid] = red[tid];
}

// ---------------------------------------------------------------------------
// Kernel 3: final scalar reduction
// loss = scale * sum_i [ log(rs[i]-e^2) + log(rs[N+i]-e^2) - 4*posdot[i] ]
// ---------------------------------------------------------------------------
__global__ void __launch_bounds__(256) finalize_kernel(const int* __restrict__ meanp,
                                                        float* __restrict__ out) {
    const int t = threadIdx.x;
    const int w = t >> 5, l = t & 31;
    __shared__ float sh[8];
    float s = 0.0f;
    for (int i = t; i < NHALF; i += 256) {
        s += (lg2_approx(g_rowsum[i] - E2) + lg2_approx(g_rowsum[NHALF + i] - E2)) * LN2F
             - 4.0f * g_posdot[i];
    }
#pragma unroll
    for (int o = 16; o; o >>= 1) s += __shfl_xor_sync(0xffffffffu, s, o);
    if (l == 0) sh[w] = s;
    __syncthreads();
    if (t == 0) {
        float tot = 0.f;
        for (int k = 0; k < 8; ++k) tot += sh[k];
        float scale = (*meanp != 0) ? (0.5f / (float)NHALF) : 0.5f;
        out[0] = tot * scale;
    }
}

// ---------------------------------------------------------------------------
extern "C" void kernel_launch(void* const* d_in, const int* in_sizes, int n_in,
                              void* d_out, int out_size) {
    (void)in_sizes; (void)n_in; (void)out_size;
    const float* z1 = (const float*)d_in[0];
    const float* z2 = (const float*)d_in[1];
    const int* meanp = (const int*)d_in[2];
    float* out = (float*)d_out;

    cudaFuncSetAttribute(gemm_rowsum_kernel,
                         cudaFuncAttributeMaxDynamicSharedMemorySize, SM_TOTAL);

    normalize_kernel<<<NHALF, DDIM>>>(z1, z2);
    gemm_rowsum_kernel<<<NT, 256, SM_TOTAL>>>();
    finalize_kernel<<<1, 256>>>(meanp, out);
}

// round 8
// speedup vs baseline: 1.8657x; 1.8657x over previous
#include <cuda_runtime.h>
#include <cuda_bf16.h>
#include <cstdint>
#include <math.h>

// ---------------------------------------------------------------------------
// Problem constants
// ---------------------------------------------------------------------------
#define NHALF 8192
#define NROWS 16384
#define DDIM 256
#define TILE 128
#define NBLK (NROWS / TILE)        // 128 row/col blocks
#define NPAIRS 8256                // NBLK*(NBLK+1)/2 upper-tri tile pairs
#define GRID_G 148                 // persistent CTAs (one wave on 148 SMs)
#define INV_TAU_LOG2E 2.8853900817779268f   // (1/tau) * log2(e), tau = 0.5
#define E2 7.38905609893065f                // exp(2.0) = refl diagonal
#define LN2F 0.6931471805599453f

#define TILE_BYTES (TILE * DDIM * 2)        // 65536 bytes (128 rows x 256 bf16)

// Scratch (static device arrays; no allocations allowed)
__device__ __align__(256) __nv_bfloat16 g_X[NROWS * DDIM];   // 8 MB normalized bf16
__device__ float g_rowsum[NROWS];
__device__ float g_posdot[NHALF];

// ---------------------------------------------------------------------------
// PTX helpers (plain sm_103-legal ISA only: ldmatrix / mma.sync / cp.async)
// ---------------------------------------------------------------------------
__device__ __forceinline__ float ex2_approx(float x) {
    float r;
    asm("ex2.approx.ftz.f32 %0, %1;" : "=f"(r) : "f"(x));
    return r;
}

__device__ __forceinline__ float lg2_approx(float x) {
    float r;
    asm("lg2.approx.ftz.f32 %0, %1;" : "=f"(r) : "f"(x));
    return r;
}

__device__ __forceinline__ uint32_t smem_u32(const void* p) {
    uint32_t a;
    asm("{ .reg .u64 t; cvta.to.shared.u64 t, %1; cvt.u32.u64 %0, t; }" : "=r"(a) : "l"(p));
    return a;
}

#define CP_COMMIT() asm volatile("cp.async.commit_group;" ::: "memory")
#define CP_WAIT1()  asm volatile("cp.async.wait_group 1;" ::: "memory")
#define CP_WAIT0()  asm volatile("cp.async.wait_group 0;" ::: "memory")

// Blocked-atom SW128 address for element (row, colb16) inside a 128x256 bf16 tile.
__device__ __forceinline__ uint32_t tile_addr(uint32_t base, int row, int colb16) {
    uint32_t byte = (uint32_t)(((row >> 3) + (colb16 >> 6) * 16) * 1024 +
                               (row & 7) * 128 + (colb16 & 63) * 2);
    byte ^= (byte >> 3) & 0x70;            // SW128 swizzle
    return base + byte;
}

// Async-copy one 128x256 bf16 tile (row-major global) into blocked-atom SW128 SMEM.
__device__ __forceinline__ void cp_tile_async(uint32_t dst_base, const char* __restrict__ src,
                                              int tid) {
#pragma unroll
    for (int k = 0; k < 16; ++k) {
        int idx = tid + k * 256;               // row*32 + q
        int row = idx >> 5;
        int q = idx & 31;
        uint32_t byte = (uint32_t)(((row >> 3) + (q >> 3) * 16) * 1024 +
                                   (row & 7) * 128 + (q & 7) * 16);
        byte ^= (byte >> 3) & 0x70;
        asm volatile("cp.async.cg.shared.global [%0], [%1], 16;"
                     :: "r"(dst_base + byte), "l"(src + (size_t)idx * 16) : "memory");
    }
}

__device__ __forceinline__ void ldsm_x4(uint32_t addr, uint32_t& r0, uint32_t& r1,
                                        uint32_t& r2, uint32_t& r3) {
    asm volatile("ldmatrix.sync.aligned.m8n8.x4.shared.b16 {%0,%1,%2,%3}, [%4];"
                 : "=r"(r0), "=r"(r1), "=r"(r2), "=r"(r3) : "r"(addr));
}

__device__ __forceinline__ void mma16816(float& c0, float& c1, float& c2, float& c3,
                                         uint32_t a0, uint32_t a1, uint32_t a2, uint32_t a3,
                                         uint32_t b0, uint32_t b1) {
    asm volatile("mma.sync.aligned.m16n8k16.row.col.f32.bf16.bf16.f32 "
                 "{%0,%1,%2,%3}, {%4,%5,%6,%7}, {%8,%9}, {%0,%1,%2,%3};"
                 : "+f"(c0), "+f"(c1), "+f"(c2), "+f"(c3)
                 : "r"(a0), "r"(a1), "r"(a2), "r"(a3), "r"(b0), "r"(b1));
}

// ---------------------------------------------------------------------------
// SMEM layout for GEMM kernel
// ---------------------------------------------------------------------------
#define SM_A 0
#define SM_B0 65536
#define SM_B1 131072
#define SM_TOTAL 196608            // 192 KB -> 1 CTA/SM

// ---------------------------------------------------------------------------
// Kernel 1: normalize rows (warp-per-row), write bf16 X = [an; bn],
//           compute pos dot (fp32), zero g_rowsum for gemm atomics.
// grid = 1024 blocks x 256 threads (8 warps = 8 input rows per block).
// ---------------------------------------------------------------------------
__global__ void __launch_bounds__(256) normalize_kernel(const float* __restrict__ z1,
                                                         const float* __restrict__ z2) {
    const int tid = threadIdx.x;
    const int wid = tid >> 5, lane = tid & 31;
    const int i = blockIdx.x * 8 + wid;        // input row [0, 8192)

    if (tid < 16) g_rowsum[(size_t)blockIdx.x * 16 + tid] = 0.0f;

    const float4* za = reinterpret_cast<const float4*>(z1 + (size_t)i * DDIM);
    const float4* zb = reinterpret_cast<const float4*>(z2 + (size_t)i * DDIM);
    float4 a0 = za[lane], a1 = za[lane + 32];
    float4 b0 = zb[lane], b1 = zb[lane + 32];

    float va = a0.x*a0.x + a0.y*a0.y + a0.z*a0.z + a0.w*a0.w
             + a1.x*a1.x + a1.y*a1.y + a1.z*a1.z + a1.w*a1.w;
    float vb = b0.x*b0.x + b0.y*b0.y + b0.z*b0.z + b0.w*b0.w
             + b1.x*b1.x + b1.y*b1.y + b1.z*b1.z + b1.w*b1.w;
    float vd = a0.x*b0.x + a0.y*b0.y + a0.z*b0.z + a0.w*b0.w
             + a1.x*b1.x + a1.y*b1.y + a1.z*b1.z + a1.w*b1.w;
#pragma unroll
    for (int o = 16; o; o >>= 1) {
        va += __shfl_xor_sync(0xffffffffu, va, o);
        vb += __shfl_xor_sync(0xffffffffu, vb, o);
        vd += __shfl_xor_sync(0xffffffffu, vd, o);
    }
    const float ia = rsqrtf(fmaxf(va, 1e-24f));   // norms ~16 >> eps
    const float ib = rsqrtf(fmaxf(vb, 1e-24f));
    if (lane == 0) g_posdot[i] = vd * ia * ib;

    uint2* oa = reinterpret_cast<uint2*>(g_X + (size_t)i * DDIM);
    uint2* ob = reinterpret_cast<uint2*>(g_X + (size_t)(NHALF + i) * DDIM);
    uint2 pa0, pa1, pb0, pb1;
    __nv_bfloat162 h;
    h = __floats2bfloat162_rn(a0.x * ia, a0.y * ia); pa0.x = *reinterpret_cast<uint32_t*>(&h);
    h = __floats2bfloat162_rn(a0.z * ia, a0.w * ia); pa0.y = *reinterpret_cast<uint32_t*>(&h);
    h = __floats2bfloat162_rn(a1.x * ia, a1.y * ia); pa1.x = *reinterpret_cast<uint32_t*>(&h);
    h = __floats2bfloat162_rn(a1.z * ia, a1.w * ia); pa1.y = *reinterpret_cast<uint32_t*>(&h);
    h = __floats2bfloat162_rn(b0.x * ib, b0.y * ib); pb0.x = *reinterpret_cast<uint32_t*>(&h);
    h = __floats2bfloat162_rn(b0.z * ib, b0.w * ib); pb0.y = *reinterpret_cast<uint32_t*>(&h);
    h = __floats2bfloat162_rn(b1.x * ib, b1.y * ib); pb1.x = *reinterpret_cast<uint32_t*>(&h);
    h = __floats2bfloat162_rn(b1.z * ib, b1.w * ib); pb1.y = *reinterpret_cast<uint32_t*>(&h);
    oa[lane] = pa0; oa[lane + 32] = pa1;
    ob[lane] = pb0; ob[lane + 32] = pb1;
}

// ---------------------------------------------------------------------------
// Kernel 2: symmetric exp-rowsum GEMM. Only upper-triangle tiles (i<=j).
// Tile (i,j): rowsums of exp -> block i; colsums of exp -> block j (skip if i==j).
// 148 persistent CTAs; each handles a contiguous range of the 64 paired strips
// (strip s = [rows i=s, tiles j=s..127] ++ [rows i=127-s, tiles j=127-s..127],
//  129 tiles, contiguous-j runs). B double-buffered via cp.async.
// ---------------------------------------------------------------------------
__global__ void __launch_bounds__(256, 1) gemm_rowsum_kernel() {
    extern __shared__ char smem[];
    const uint32_t sbase = smem_u32(smem);
    const int tid = threadIdx.x;
    const int wid = tid >> 5, lane = tid & 31;
    const int wm = wid >> 2;          // 0..1: 64-row half of i-block
    const int wn = wid & 3;           // 0..3: 32-col quarter of j-block

    const int a_row_in = lane & 15;
    const int a_col_in = (lane >> 4) * 8;
    const int b_row_in = (lane & 7) + ((lane >> 4) & 1) * 8;
    const int b_col_in = ((lane >> 3) & 1) * 8;

    const char* Xb = reinterpret_cast<const char*>(g_X);

    int g        = (int)(((long long)blockIdx.x * NPAIRS) / GRID_G);
    const int g1 = (int)(((long long)(blockIdx.x + 1) * NPAIRS) / GRID_G);

    while (g < g1) {
        // decode run: strip s, local index t0; boundary b between the two i-legs
        const int s  = g / 129;
        const int t0 = g - s * 129;
        const int bnd = 128 - s;
        int i, j0, rend;
        if (t0 < bnd) { i = s;       j0 = s + t0;                rend = s * 129 + bnd; }
        else          { i = 127 - s; j0 = (127 - s) + (t0 - bnd); rend = (s + 1) * 129; }
        int cnt = min(rend, g1) - g;

        // ---- stream run: fixed i, j = j0..j0+cnt-1 ----
        cp_tile_async(sbase + SM_A, Xb + (size_t)i * TILE_BYTES, tid);
        CP_COMMIT();
        cp_tile_async(sbase + SM_B0, Xb + (size_t)j0 * TILE_BYTES, tid);
        CP_COMMIT();
        if (cnt > 1) cp_tile_async(sbase + SM_B1, Xb + (size_t)(j0 + 1) * TILE_BYTES, tid);
        CP_COMMIT();   // may be an empty group (cnt==1)

        float rowacc[8];
#pragma unroll
        for (int r = 0; r < 8; ++r) rowacc[r] = 0.0f;

        for (int t = 0; t < cnt; ++t) {
            // last tile's B may be the newest group -> full drain there
            if (t == cnt - 1) CP_WAIT0(); else CP_WAIT1();
            __syncthreads();

            const int j = j0 + t;
            const uint32_t bbase = sbase + ((t & 1) ? SM_B1 : SM_B0);

            float c[4][4][4];
#pragma unroll
            for (int mf = 0; mf < 4; ++mf)
#pragma unroll
                for (int nf = 0; nf < 4; ++nf)
#pragma unroll
                    for (int r = 0; r < 4; ++r) c[mf][nf][r] = 0.0f;

#pragma unroll
            for (int ks = 0; ks < 16; ++ks) {
                const int kcol = ks * 16;
                uint32_t a[4][4];
#pragma unroll
                for (int mf = 0; mf < 4; ++mf)
                    ldsm_x4(tile_addr(sbase + SM_A, wm * 64 + mf * 16 + a_row_in,
                                      kcol + a_col_in),
                            a[mf][0], a[mf][1], a[mf][2], a[mf][3]);
                uint32_t b[4][2];
#pragma unroll
                for (int p = 0; p < 2; ++p) {
                    uint32_t r0, r1, r2, r3;
                    ldsm_x4(tile_addr(bbase, wn * 32 + p * 16 + b_row_in,
                                      kcol + b_col_in),
                            r0, r1, r2, r3);
                    b[p * 2 + 0][0] = r0; b[p * 2 + 0][1] = r1;
                    b[p * 2 + 1][0] = r2; b[p * 2 + 1][1] = r3;
                }
#pragma unroll
                for (int mf = 0; mf < 4; ++mf)
#pragma unroll
                    for (int nf = 0; nf < 4; ++nf)
                        mma16816(c[mf][nf][0], c[mf][nf][1], c[mf][nf][2], c[mf][nf][3],
                                 a[mf][0], a[mf][1], a[mf][2], a[mf][3],
                                 b[nf][0], b[nf][1]);
            }

            // exp epilogue: per-entry exp feeds BOTH row sums (block i) and
            // col sums (block j). acc layout: c0/c1 row=lane>>2, cols 2*(lane&3)+{0,1};
            // c2/c3 same cols, row+8.
            float colacc[8];
#pragma unroll
            for (int r = 0; r < 8; ++r) colacc[r] = 0.0f;
#pragma unroll
            for (int mf = 0; mf < 4; ++mf) {
                float s0 = 0.f, s1 = 0.f;
#pragma unroll
                for (int nf = 0; nf < 4; ++nf) {
                    float e0 = ex2_approx(c[mf][nf][0] * INV_TAU_LOG2E);
                    float e1 = ex2_approx(c[mf][nf][1] * INV_TAU_LOG2E);
                    float e2 = ex2_approx(c[mf][nf][2] * INV_TAU_LOG2E);
                    float e3 = ex2_approx(c[mf][nf][3] * INV_TAU_LOG2E);
                    s0 += e0 + e1;
                    s1 += e2 + e3;
                    colacc[nf * 2 + 0] += e0 + e2;
                    colacc[nf * 2 + 1] += e1 + e3;
                }
                rowacc[mf * 2 + 0] += s0;
                rowacc[mf * 2 + 1] += s1;
            }

            if (j != i) {
                // col sums: reduce over rows (lanes with same lane&3) then global
#pragma unroll
                for (int r = 0; r < 8; ++r) {
                    float v = colacc[r];
                    v += __shfl_xor_sync(0xffffffffu, v, 4);
                    v += __shfl_xor_sync(0xffffffffu, v, 8);
                    v += __shfl_xor_sync(0xffffffffu, v, 16);
                    if (lane < 4)
                        atomicAdd(&g_rowsum[(size_t)j * TILE + wn * 32 + (r >> 1) * 8 +
                                            lane * 2 + (r & 1)], v);
                }
            }

            __syncthreads();       // everyone done reading buf[t&1]
            if (t + 2 < cnt) {
                cp_tile_async(bbase, Xb + (size_t)(j + 2) * TILE_BYTES, tid);
                CP_COMMIT();
            }
        }

        // row sums for block i: reduce over cols (lane&3 group) then global
#pragma unroll
        for (int r = 0; r < 8; ++r) {
            float v = rowacc[r];
            v += __shfl_xor_sync(0xffffffffu, v, 1);
            v += __shfl_xor_sync(0xffffffffu, v, 2);
            if ((lane & 3) == 0)
                atomicAdd(&g_rowsum[(size_t)i * TILE + wm * 64 + (r >> 1) * 16 +
                                    (lane >> 2) + (r & 1) * 8], v);
        }

        g += cnt;
    }
}

// ---------------------------------------------------------------------------
// Kernel 3: final scalar reduction
// loss = scale * sum_i [ log(rs[i]-e^2) + log(rs[N+i]-e^2) - 4*posdot[i] ]
// ---------------------------------------------------------------------------
__global__ void __launch_bounds__(256) finalize_kernel(const int* __restrict__ meanp,
                                                        float* __restrict__ out) {
    const int t = threadIdx.x;
    const int w = t >> 5, l = t & 31;
    __shared__ float sh[8];
    float s = 0.0f;
    for (int i = t; i < NHALF; i += 256) {
        s += (lg2_approx(g_rowsum[i] - E2) + lg2_approx(g_rowsum[NHALF + i] - E2)) * LN2F
             - 4.0f * g_posdot[i];
    }
#pragma unroll
    for (int o = 16; o; o >>= 1) s += __shfl_xor_sync(0xffffffffu, s, o);
    if (l == 0) sh[w] = s;
    __syncthreads();
    if (t == 0) {
        float tot = 0.f;
        for (int k = 0; k < 8; ++k) tot += sh[k];
        float scale = (*meanp != 0) ? (0.5f / (float)NHALF) : 0.5f;
        out[0] = tot * scale;
    }
}

// ---------------------------------------------------------------------------
extern "C" void kernel_launch(void* const* d_in, const int* in_sizes, int n_in,
                              void* d_out, int out_size) {
    (void)in_sizes; (void)n_in; (void)out_size;
    const float* z1 = (const float*)d_in[0];
    const float* z2 = (const float*)d_in[1];
    const int* meanp = (const int*)d_in[2];
    float* out = (float*)d_out;

    cudaFuncSetAttribute(gemm_rowsum_kernel,
                         cudaFuncAttributeMaxDynamicSharedMemorySize, SM_TOTAL);

    normalize_kernel<<<NHALF / 8, 256>>>(z1, z2);
    gemm_rowsum_kernel<<<GRID_G, 256, SM_TOTAL>>>();
    finalize_kernel<<<1, 256>>>(meanp, out);
}